// round 2
// baseline (speedup 1.0000x reference)
#include <cuda_runtime.h>
#include <cuda_bf16.h>
#include <math.h>

// Problem shape (fixed by the dataset problem)
#define NN 100000
#define EE 1600000
#define FIN 128
#define FOUT 32
#define ALPHA 0.2f

// Scratch (no cudaMalloc allowed -> __device__ globals)
__device__ __align__(16) float g_Wx[(size_t)NN * FOUT];   // 12.8 MB
__device__ float g_as[NN];                  // alpha_src per node
__device__ float g_ad[NN];                  // alpha_dst per node
__device__ float g_m[NN];                   // segment max
__device__ float g_s[NN];                   // segment sum of exp
__device__ float g_exp[EE];                 // exp(e - m[src]) per edge

// ---------------------------------------------------------------------------
// K0: init scratch + zero output
// ---------------------------------------------------------------------------
__global__ void k_init(float* __restrict__ out, int n, int total_out) {
    int i = blockIdx.x * blockDim.x + threadIdx.x;
    int stride = gridDim.x * blockDim.x;
    for (int j = i; j < total_out; j += stride) out[j] = 0.0f;
    for (int j = i; j < n; j += stride) {
        g_m[j] = -INFINITY;
        g_s[j] = 0.0f;
    }
}

// ---------------------------------------------------------------------------
// K1: Wx = x @ W  (one warp per row, lane = output column),
//     plus alpha_src[row] = Wx[row]·a[0:32], alpha_dst[row] = Wx[row]·a[32:64]
// ---------------------------------------------------------------------------
__global__ __launch_bounds__(256) void k_gemm_alpha(
    const float* __restrict__ x, const float* __restrict__ W,
    const float* __restrict__ a, int n)
{
    __shared__ float Ws[FIN * FOUT];   // 16 KB
    for (int i = threadIdx.x; i < FIN * FOUT; i += blockDim.x) Ws[i] = W[i];
    __syncthreads();

    int warp = threadIdx.x >> 5;
    int lane = threadIdx.x & 31;
    int row = blockIdx.x * 8 + warp;
    if (row >= n) return;

    const float* xr = x + (size_t)row * FIN;
    // coalesced row load, distributed across lanes
    float x0 = xr[lane];
    float x1 = xr[32 + lane];
    float x2 = xr[64 + lane];
    float x3 = xr[96 + lane];

    float acc = 0.0f;
#pragma unroll
    for (int k = 0; k < 32; k++)
        acc = fmaf(__shfl_sync(0xFFFFFFFFu, x0, k), Ws[k * FOUT + lane], acc);
#pragma unroll
    for (int k = 0; k < 32; k++)
        acc = fmaf(__shfl_sync(0xFFFFFFFFu, x1, k), Ws[(32 + k) * FOUT + lane], acc);
#pragma unroll
    for (int k = 0; k < 32; k++)
        acc = fmaf(__shfl_sync(0xFFFFFFFFu, x2, k), Ws[(64 + k) * FOUT + lane], acc);
#pragma unroll
    for (int k = 0; k < 32; k++)
        acc = fmaf(__shfl_sync(0xFFFFFFFFu, x3, k), Ws[(96 + k) * FOUT + lane], acc);

    g_Wx[(size_t)row * FOUT + lane] = acc;

    float vs = acc * a[lane];
    float vd = acc * a[FOUT + lane];
#pragma unroll
    for (int o = 16; o > 0; o >>= 1) {
        vs += __shfl_xor_sync(0xFFFFFFFFu, vs, o);
        vd += __shfl_xor_sync(0xFFFFFFFFu, vd, o);
    }
    if (lane == 0) {
        g_as[row] = vs;
        g_ad[row] = vd;
    }
}

// float atomic max via dual int/uint atomics (valid with init = -inf)
__device__ __forceinline__ void atomicMaxF(float* addr, float v) {
    if (v >= 0.0f) atomicMax((int*)addr, __float_as_int(v));
    else           atomicMin((unsigned int*)addr, __float_as_uint(v));
}

__device__ __forceinline__ float leaky(float v) {
    return v >= 0.0f ? v : ALPHA * v;
}

// ---------------------------------------------------------------------------
// K2: per-edge leaky-relu score, segment max over src
// ---------------------------------------------------------------------------
__global__ __launch_bounds__(256) void k_edge_max(
    const int* __restrict__ ei, int E)
{
    int e = blockIdx.x * blockDim.x + threadIdx.x;
    if (e >= E) return;
    int s = ei[e];
    int d = ei[E + e];
    float v = leaky(g_as[s] + g_ad[d]);
    atomicMaxF(&g_m[s], v);
}

// ---------------------------------------------------------------------------
// K3: exp(e - m[src]), store per-edge, segment sum over src
// ---------------------------------------------------------------------------
__global__ __launch_bounds__(256) void k_edge_sumexp(
    const int* __restrict__ ei, int E)
{
    int e = blockIdx.x * blockDim.x + threadIdx.x;
    if (e >= E) return;
    int s = ei[e];
    int d = ei[E + e];
    float v = leaky(g_as[s] + g_ad[d]);
    float ev = __expf(v - g_m[s]);
    g_exp[e] = ev;
    atomicAdd(&g_s[s], ev);
}

// ---------------------------------------------------------------------------
// K4: h[src] += (exp/s[src]) * Wx[dst]  — 8 threads per edge, float4 RED
// ---------------------------------------------------------------------------
__global__ __launch_bounds__(256) void k_edge_agg(
    const int* __restrict__ ei, float* __restrict__ out, int E)
{
    long long idx = (long long)blockIdx.x * blockDim.x + threadIdx.x;
    if (idx >= (long long)E * 8) return;
    int e = (int)(idx >> 3);
    int g = (int)(idx & 7);
    int s = ei[e];
    int d = ei[E + e];
    float att = g_exp[e] / g_s[s];
    const float4 w = *reinterpret_cast<const float4*>(g_Wx + (size_t)d * FOUT + g * 4);
    float* p = out + (size_t)s * FOUT + g * 4;
    asm volatile(
        "red.global.add.v4.f32 [%0], {%1, %2, %3, %4};"
        :: "l"(p), "f"(w.x * att), "f"(w.y * att), "f"(w.z * att), "f"(w.w * att)
        : "memory");
}

// ---------------------------------------------------------------------------
// K5: ELU epilogue in place
// ---------------------------------------------------------------------------
__global__ __launch_bounds__(256) void k_elu(float* __restrict__ out, int total) {
    int i = blockIdx.x * blockDim.x + threadIdx.x;
    if (i >= total) return;
    float h = out[i];
    out[i] = h > 0.0f ? h : expm1f(h);
}

// ---------------------------------------------------------------------------
extern "C" void kernel_launch(void* const* d_in, const int* in_sizes, int n_in,
                              void* d_out, int out_size)
{
    const float* x  = (const float*)d_in[0];       // (N, 128)
    const float* W  = (const float*)d_in[1];       // (128, 32)
    const float* a  = (const float*)d_in[2];       // (64, 1)
    const int*   ei = (const int*)d_in[3];         // (2, E) int32 (jax x64 disabled)
    float* out = (float*)d_out;                    // (N, 32)

    const int n = in_sizes[0] / FIN;
    const int E = in_sizes[3] / 2;
    const int total_out = n * FOUT;

    k_init<<<512, 256>>>(out, n, total_out);
    k_gemm_alpha<<<(n + 7) / 8, 256>>>(x, W, a, n);
    k_edge_max<<<(E + 255) / 256, 256>>>(ei, E);
    k_edge_sumexp<<<(E + 255) / 256, 256>>>(ei, E);
    {
        long long work = (long long)E * 8;
        int blocks = (int)((work + 255) / 256);
        k_edge_agg<<<blocks, 256>>>(ei, out, E);
    }
    k_elu<<<(total_out + 255) / 256, 256>>>(out, total_out);
}

// round 3
// speedup vs baseline: 1.0304x; 1.0304x over previous
#include <cuda_runtime.h>
#include <cuda_bf16.h>
#include <math.h>

#define NN 100000
#define EE 1600000
#define FIN 128
#define FOUT 32
#define ALPHA 0.2f
#define NEG_INF (-1.0f/0.0f)

#define SCAN_CH 512
#define SCAN_BLOCKS ((NN + SCAN_CH - 1) / SCAN_CH)   // 196

// Scratch (__device__ globals; no cudaMalloc allowed)
__device__ __align__(16) float g_Wx[(size_t)NN * FOUT];   // 12.8 MB
__device__ float g_as[NN];
__device__ float g_ad[NN];
__device__ int   g_cnt[NN];
__device__ int   g_rowptr[NN + 1];
__device__ int   g_wpos[NN];
__device__ int   g_bsum[SCAN_BLOCKS];
__device__ int   g_boff[SCAN_BLOCKS];
__device__ int   g_edst[EE];

// ---------------------------------------------------------------------------
// K0: zero histogram counters
// ---------------------------------------------------------------------------
__global__ void k_init(int n) {
    int i = blockIdx.x * blockDim.x + threadIdx.x;
    int stride = gridDim.x * blockDim.x;
    for (int j = i; j < n; j += stride) g_cnt[j] = 0;
}

// ---------------------------------------------------------------------------
// K1: Wx = x @ W (one warp per row, lane = output col) + alpha projections
// ---------------------------------------------------------------------------
__global__ __launch_bounds__(256) void k_gemm_alpha(
    const float* __restrict__ x, const float* __restrict__ W,
    const float* __restrict__ a, int n)
{
    __shared__ float Ws[FIN * FOUT];   // 16 KB
    for (int i = threadIdx.x; i < FIN * FOUT; i += blockDim.x) Ws[i] = W[i];
    __syncthreads();

    int warp = threadIdx.x >> 5;
    int lane = threadIdx.x & 31;
    int row = blockIdx.x * 8 + warp;
    if (row >= n) return;

    const float* xr = x + (size_t)row * FIN;
    float x0 = xr[lane];
    float x1 = xr[32 + lane];
    float x2 = xr[64 + lane];
    float x3 = xr[96 + lane];

    float acc = 0.0f;
#pragma unroll
    for (int k = 0; k < 32; k++)
        acc = fmaf(__shfl_sync(0xFFFFFFFFu, x0, k), Ws[k * FOUT + lane], acc);
#pragma unroll
    for (int k = 0; k < 32; k++)
        acc = fmaf(__shfl_sync(0xFFFFFFFFu, x1, k), Ws[(32 + k) * FOUT + lane], acc);
#pragma unroll
    for (int k = 0; k < 32; k++)
        acc = fmaf(__shfl_sync(0xFFFFFFFFu, x2, k), Ws[(64 + k) * FOUT + lane], acc);
#pragma unroll
    for (int k = 0; k < 32; k++)
        acc = fmaf(__shfl_sync(0xFFFFFFFFu, x3, k), Ws[(96 + k) * FOUT + lane], acc);

    g_Wx[(size_t)row * FOUT + lane] = acc;

    float vs = acc * a[lane];
    float vd = acc * a[FOUT + lane];
#pragma unroll
    for (int o = 16; o > 0; o >>= 1) {
        vs += __shfl_xor_sync(0xFFFFFFFFu, vs, o);
        vd += __shfl_xor_sync(0xFFFFFFFFu, vd, o);
    }
    if (lane == 0) {
        g_as[row] = vs;
        g_ad[row] = vd;
    }
}

// ---------------------------------------------------------------------------
// K2: histogram of src
// ---------------------------------------------------------------------------
__global__ __launch_bounds__(256) void k_hist(const int* __restrict__ ei, int E) {
    int e = blockIdx.x * blockDim.x + threadIdx.x;
    if (e >= E) return;
    atomicAdd(&g_cnt[ei[e]], 1);
}

// ---------------------------------------------------------------------------
// K3a/b/c: two-level exclusive scan of g_cnt -> g_rowptr (and g_wpos copy)
// ---------------------------------------------------------------------------
__global__ __launch_bounds__(SCAN_CH) void k_scan1(int n) {
    __shared__ int sm[SCAN_CH];
    int idx = blockIdx.x * SCAN_CH + threadIdx.x;
    sm[threadIdx.x] = (idx < n) ? g_cnt[idx] : 0;
    __syncthreads();
    for (int off = SCAN_CH / 2; off > 0; off >>= 1) {
        if (threadIdx.x < off) sm[threadIdx.x] += sm[threadIdx.x + off];
        __syncthreads();
    }
    if (threadIdx.x == 0) g_bsum[blockIdx.x] = sm[0];
}

__global__ __launch_bounds__(256) void k_scan2(int nb, int n, int E) {
    __shared__ int sm[256];
    int tid = threadIdx.x;
    int v = (tid < nb) ? g_bsum[tid] : 0;
    sm[tid] = v;
    __syncthreads();
    for (int off = 1; off < 256; off <<= 1) {
        int t = (tid >= off) ? sm[tid - off] : 0;
        __syncthreads();
        sm[tid] += t;
        __syncthreads();
    }
    if (tid < nb) g_boff[tid] = sm[tid] - v;   // exclusive
    if (tid == 0) g_rowptr[n] = E;
}

__global__ __launch_bounds__(SCAN_CH) void k_scan3(int n) {
    __shared__ int sm[SCAN_CH];
    int tid = threadIdx.x;
    int idx = blockIdx.x * SCAN_CH + tid;
    int v = (idx < n) ? g_cnt[idx] : 0;
    sm[tid] = v;
    __syncthreads();
    for (int off = 1; off < SCAN_CH; off <<= 1) {
        int t = (tid >= off) ? sm[tid - off] : 0;
        __syncthreads();
        sm[tid] += t;
        __syncthreads();
    }
    if (idx < n) {
        int ex = g_boff[blockIdx.x] + sm[tid] - v;   // exclusive scan value
        g_rowptr[idx] = ex;
        g_wpos[idx] = ex;
    }
}

// ---------------------------------------------------------------------------
// K4: scatter dst indices into CSR slots
// ---------------------------------------------------------------------------
__global__ __launch_bounds__(256) void k_scatter(const int* __restrict__ ei, int E) {
    int e = blockIdx.x * blockDim.x + threadIdx.x;
    if (e >= E) return;
    int s = ei[e];
    int d = ei[E + e];
    int pos = atomicAdd(&g_wpos[s], 1);
    g_edst[pos] = d;
}

__device__ __forceinline__ float leaky(float v) {
    return v >= 0.0f ? v : ALPHA * v;
}

// ---------------------------------------------------------------------------
// K5: fused softmax + aggregation + ELU. One warp per node, no atomics.
// ---------------------------------------------------------------------------
__global__ __launch_bounds__(256) void k_agg(float* __restrict__ out, int n) {
    int u = (blockIdx.x * blockDim.x + threadIdx.x) >> 5;
    int lane = threadIdx.x & 31;
    if (u >= n) return;

    int beg = g_rowptr[u];
    int end = g_rowptr[u + 1];
    float* op = out + (size_t)u * FOUT + lane;

    if (beg == end) {            // isolated node: h = 0 -> elu(0) = 0
        *op = 0.0f;
        return;
    }

    float a_s = g_as[u];

    // Pass 1: online (max, sum-of-exp) per lane over strided edges
    float m_l = NEG_INF, s_l = 0.0f;
    for (int i = beg + lane; i < end; i += 32) {
        int d = g_edst[i];
        float v = leaky(a_s + g_ad[d]);
        if (v > m_l) {
            s_l = s_l * __expf(m_l - v) + 1.0f;   // expf(-inf)=0 on first hit
            m_l = v;
        } else {
            s_l += __expf(v - m_l);
        }
    }
    // warp combine (guard -inf lanes: factor forced to 0)
#pragma unroll
    for (int o = 16; o > 0; o >>= 1) {
        float mo = __shfl_xor_sync(0xFFFFFFFFu, m_l, o);
        float so = __shfl_xor_sync(0xFFFFFFFFu, s_l, o);
        float mn = fmaxf(m_l, mo);
        float f1 = (m_l > NEG_INF) ? __expf(m_l - mn) : 0.0f;
        float f2 = (mo  > NEG_INF) ? __expf(mo  - mn) : 0.0f;
        s_l = s_l * f1 + so * f2;
        m_l = mn;
    }
    float inv = 1.0f / s_l;      // deg>=1 -> s_l >= exp(0) contribution > 0

    // Pass 2: accumulate att * Wx[dst]; lane = feature column, coalesced rows
    float acc = 0.0f;
    for (int chunk = beg; chunk < end; chunk += 32) {
        int i = chunk + lane;
        int d = 0;
        float ev = 0.0f;
        if (i < end) {
            d = g_edst[i];
            ev = __expf(leaky(a_s + g_ad[d]) - m_l);
        }
        int cnt = min(32, end - chunk);
        for (int k = 0; k < cnt; k++) {
            float att = __shfl_sync(0xFFFFFFFFu, ev, k) * inv;
            int dk = __shfl_sync(0xFFFFFFFFu, d, k);
            acc = fmaf(att, g_Wx[(size_t)dk * FOUT + lane], acc);
        }
    }

    *op = acc > 0.0f ? acc : expm1f(acc);
}

// ---------------------------------------------------------------------------
extern "C" void kernel_launch(void* const* d_in, const int* in_sizes, int n_in,
                              void* d_out, int out_size)
{
    const float* x  = (const float*)d_in[0];   // (N, 128)
    const float* W  = (const float*)d_in[1];   // (128, 32)
    const float* a  = (const float*)d_in[2];   // (64, 1)
    const int*   ei = (const int*)d_in[3];     // (2, E) int32
    float* out = (float*)d_out;                // (N, 32)

    const int n = in_sizes[0] / FIN;
    const int E = in_sizes[3] / 2;
    const int nb = (n + SCAN_CH - 1) / SCAN_CH;

    k_init<<<256, 256>>>(n);
    k_gemm_alpha<<<(n + 7) / 8, 256>>>(x, W, a, n);
    k_hist<<<(E + 255) / 256, 256>>>(ei, E);
    k_scan1<<<nb, SCAN_CH>>>(n);
    k_scan2<<<1, 256>>>(nb, n, E);
    k_scan3<<<nb, SCAN_CH>>>(n);
    k_scatter<<<(E + 255) / 256, 256>>>(ei, E);
    k_agg<<<(n * 32 + 255) / 256, 256>>>(out, n);
}

// round 4
// speedup vs baseline: 1.1297x; 1.0963x over previous
#include <cuda_runtime.h>
#include <cuda_bf16.h>
#include <math.h>

#define NN 100000
#define EE 1600000
#define FIN 128
#define FOUT 32
#define ALPHA 0.2f

#define SCAN_CH 512
#define SCAN_BLOCKS ((NN + SCAN_CH - 1) / SCAN_CH)   // 196

// Scratch (__device__ globals; no cudaMalloc allowed)
__device__ __align__(16) float g_Wx[(size_t)NN * FOUT];   // 12.8 MB
__device__ float g_as[NN];
__device__ float g_ad[NN];
__device__ int   g_cnt[NN];
__device__ int   g_rowptr[NN + 1];
__device__ int   g_wpos[NN];
__device__ int   g_bsum[SCAN_BLOCKS];
__device__ int   g_boff[SCAN_BLOCKS];
__device__ int   g_edst[EE];

// ---------------------------------------------------------------------------
// K0: zero histogram counters
// ---------------------------------------------------------------------------
__global__ void k_init(int n) {
    int i = blockIdx.x * blockDim.x + threadIdx.x;
    int stride = gridDim.x * blockDim.x;
    for (int j = i; j < n; j += stride) g_cnt[j] = 0;
}

// ---------------------------------------------------------------------------
// K1: Wx = x @ W (one warp per row, lane = output col) + alpha projections
// ---------------------------------------------------------------------------
__global__ __launch_bounds__(256) void k_gemm_alpha(
    const float* __restrict__ x, const float* __restrict__ W,
    const float* __restrict__ a, int n)
{
    __shared__ float Ws[FIN * FOUT];   // 16 KB
    for (int i = threadIdx.x; i < FIN * FOUT; i += blockDim.x) Ws[i] = W[i];
    __syncthreads();

    int warp = threadIdx.x >> 5;
    int lane = threadIdx.x & 31;
    int row = blockIdx.x * 8 + warp;
    if (row >= n) return;

    const float* xr = x + (size_t)row * FIN;
    float x0 = xr[lane];
    float x1 = xr[32 + lane];
    float x2 = xr[64 + lane];
    float x3 = xr[96 + lane];

    float acc = 0.0f;
#pragma unroll
    for (int k = 0; k < 32; k++)
        acc = fmaf(__shfl_sync(0xFFFFFFFFu, x0, k), Ws[k * FOUT + lane], acc);
#pragma unroll
    for (int k = 0; k < 32; k++)
        acc = fmaf(__shfl_sync(0xFFFFFFFFu, x1, k), Ws[(32 + k) * FOUT + lane], acc);
#pragma unroll
    for (int k = 0; k < 32; k++)
        acc = fmaf(__shfl_sync(0xFFFFFFFFu, x2, k), Ws[(64 + k) * FOUT + lane], acc);
#pragma unroll
    for (int k = 0; k < 32; k++)
        acc = fmaf(__shfl_sync(0xFFFFFFFFu, x3, k), Ws[(96 + k) * FOUT + lane], acc);

    g_Wx[(size_t)row * FOUT + lane] = acc;

    float vs = acc * a[lane];
    float vd = acc * a[FOUT + lane];
#pragma unroll
    for (int o = 16; o > 0; o >>= 1) {
        vs += __shfl_xor_sync(0xFFFFFFFFu, vs, o);
        vd += __shfl_xor_sync(0xFFFFFFFFu, vd, o);
    }
    if (lane == 0) {
        g_as[row] = vs;
        g_ad[row] = vd;
    }
}

// ---------------------------------------------------------------------------
// K2: histogram of src
// ---------------------------------------------------------------------------
__global__ __launch_bounds__(256) void k_hist(const int* __restrict__ ei, int E) {
    int e = blockIdx.x * blockDim.x + threadIdx.x;
    if (e >= E) return;
    atomicAdd(&g_cnt[ei[e]], 1);
}

// ---------------------------------------------------------------------------
// K3a/b/c: two-level exclusive scan of g_cnt -> g_rowptr (and g_wpos copy)
// ---------------------------------------------------------------------------
__global__ __launch_bounds__(SCAN_CH) void k_scan1(int n) {
    __shared__ int sm[SCAN_CH];
    int idx = blockIdx.x * SCAN_CH + threadIdx.x;
    sm[threadIdx.x] = (idx < n) ? g_cnt[idx] : 0;
    __syncthreads();
    for (int off = SCAN_CH / 2; off > 0; off >>= 1) {
        if (threadIdx.x < off) sm[threadIdx.x] += sm[threadIdx.x + off];
        __syncthreads();
    }
    if (threadIdx.x == 0) g_bsum[blockIdx.x] = sm[0];
}

__global__ __launch_bounds__(256) void k_scan2(int nb, int n, int E) {
    __shared__ int sm[256];
    int tid = threadIdx.x;
    int v = (tid < nb) ? g_bsum[tid] : 0;
    sm[tid] = v;
    __syncthreads();
    for (int off = 1; off < 256; off <<= 1) {
        int t = (tid >= off) ? sm[tid - off] : 0;
        __syncthreads();
        sm[tid] += t;
        __syncthreads();
    }
    if (tid < nb) g_boff[tid] = sm[tid] - v;   // exclusive
    if (tid == 0) g_rowptr[n] = E;
}

__global__ __launch_bounds__(SCAN_CH) void k_scan3(int n) {
    __shared__ int sm[SCAN_CH];
    int tid = threadIdx.x;
    int idx = blockIdx.x * SCAN_CH + tid;
    int v = (idx < n) ? g_cnt[idx] : 0;
    sm[tid] = v;
    __syncthreads();
    for (int off = 1; off < SCAN_CH; off <<= 1) {
        int t = (tid >= off) ? sm[tid - off] : 0;
        __syncthreads();
        sm[tid] += t;
        __syncthreads();
    }
    if (idx < n) {
        int ex = g_boff[blockIdx.x] + sm[tid] - v;   // exclusive scan value
        g_rowptr[idx] = ex;
        g_wpos[idx] = ex;
    }
}

// ---------------------------------------------------------------------------
// K4: scatter dst indices into CSR slots
// ---------------------------------------------------------------------------
__global__ __launch_bounds__(256) void k_scatter(const int* __restrict__ ei, int E) {
    int e = blockIdx.x * blockDim.x + threadIdx.x;
    if (e >= E) return;
    int s = ei[e];
    int d = ei[E + e];
    int pos = atomicAdd(&g_wpos[s], 1);
    g_edst[pos] = d;
}

__device__ __forceinline__ float leaky(float v) {
    return v >= 0.0f ? v : ALPHA * v;
}

// ---------------------------------------------------------------------------
// K5: fused softmax + aggregation + ELU, ONE pass (softmax shift-invariance:
// h = (sum ev*Wx[dst]) / (sum ev), no max subtraction needed for this data).
// One warp per node: 4 edges in parallel (subgroups of 8 lanes), each lane
// holds float4 of the 32 features -> 4 independent 128B gathers in flight.
// ---------------------------------------------------------------------------
__global__ __launch_bounds__(256) void k_agg(float* __restrict__ out, int n) {
    int u = (blockIdx.x * blockDim.x + threadIdx.x) >> 5;
    int lane = threadIdx.x & 31;
    if (u >= n) return;

    int beg = g_rowptr[u];
    int end = g_rowptr[u + 1];
    float4* op = reinterpret_cast<float4*>(out + (size_t)u * FOUT);

    if (beg == end) {            // isolated node: h = 0 -> elu(0) = 0
        if (lane < 8) op[lane] = make_float4(0.f, 0.f, 0.f, 0.f);
        return;
    }

    float a_s = g_as[u];
    int sub = lane >> 3;         // edge subgroup 0..3
    int fl  = lane & 7;          // feature float4 index 0..7

    float4 acc = make_float4(0.f, 0.f, 0.f, 0.f);
    float ssum = 0.0f;
    const float4* Wx4 = reinterpret_cast<const float4*>(g_Wx);

    for (int i = beg + sub; i < end; i += 4) {
        int d = g_edst[i];                        // broadcast within subgroup
        float ev = __expf(leaky(a_s + g_ad[d]));
        float4 w = Wx4[(size_t)d * 8 + fl];       // coalesced 128B per subgroup
        acc.x = fmaf(ev, w.x, acc.x);
        acc.y = fmaf(ev, w.y, acc.y);
        acc.z = fmaf(ev, w.z, acc.z);
        acc.w = fmaf(ev, w.w, acc.w);
        ssum += ev;
    }

    // combine the 4 subgroups (lanes with equal fl): xor 8, then xor 16
#pragma unroll
    for (int o = 8; o <= 16; o <<= 1) {
        acc.x += __shfl_xor_sync(0xFFFFFFFFu, acc.x, o);
        acc.y += __shfl_xor_sync(0xFFFFFFFFu, acc.y, o);
        acc.z += __shfl_xor_sync(0xFFFFFFFFu, acc.z, o);
        acc.w += __shfl_xor_sync(0xFFFFFFFFu, acc.w, o);
        ssum  += __shfl_xor_sync(0xFFFFFFFFu, ssum, o);
    }

    if (lane < 8) {
        float inv = 1.0f / ssum;
        float hx = acc.x * inv, hy = acc.y * inv, hz = acc.z * inv, hw = acc.w * inv;
        float4 r;
        r.x = hx > 0.f ? hx : expm1f(hx);
        r.y = hy > 0.f ? hy : expm1f(hy);
        r.z = hz > 0.f ? hz : expm1f(hz);
        r.w = hw > 0.f ? hw : expm1f(hw);
        op[lane] = r;
    }
}

// ---------------------------------------------------------------------------
extern "C" void kernel_launch(void* const* d_in, const int* in_sizes, int n_in,
                              void* d_out, int out_size)
{
    const float* x  = (const float*)d_in[0];   // (N, 128)
    const float* W  = (const float*)d_in[1];   // (128, 32)
    const float* a  = (const float*)d_in[2];   // (64, 1)
    const int*   ei = (const int*)d_in[3];     // (2, E) int32
    float* out = (float*)d_out;                // (N, 32)

    const int n = in_sizes[0] / FIN;
    const int E = in_sizes[3] / 2;
    const int nb = (n + SCAN_CH - 1) / SCAN_CH;

    k_init<<<256, 256>>>(n);
    k_gemm_alpha<<<(n + 7) / 8, 256>>>(x, W, a, n);
    k_hist<<<(E + 255) / 256, 256>>>(ei, E);
    k_scan1<<<nb, SCAN_CH>>>(n);
    k_scan2<<<1, 256>>>(nb, n, E);
    k_scan3<<<nb, SCAN_CH>>>(n);
    k_scatter<<<(E + 255) / 256, 256>>>(ei, E);
    k_agg<<<(n * 32 + 255) / 256, 256>>>(out, n);
}